// round 13
// baseline (speedup 1.0000x reference)
#include <cuda_runtime.h>
#include <cuda_fp16.h>

#define Hd 1024
#define Wd 1024
#define Bd 16

// Scratch: per-pixel packed {t1 = exp(-2 rb^2), s2} as half2 (4B/px);
// per-block s2 maxima; completion counter; per-batch 1/(2*gamma^2).
__device__ __half2 d_ts[(size_t)Bd * Hd * Wd];
__device__ float d_blockmax[Bd * 128];
__device__ unsigned int d_counter = 0;
__device__ float d_inv2g2[Bd];

// Separable 1D Gaussian weights (outer(w,w) == gaussian_kernel(5,10)).
#define W0 0.19800304f
#define W1 0.20099548f
#define W2 0.20200297f

// Tile geometry: 128 wide x 64 tall, halo 4.
#define SGS 136   // sgray stride (floats), 72 rows
#define SHS 132   // shb stride, 72 rows (cols 0..131)
#define SGT 132   // sg stride, 68 rows (overlays sgray)
#define SGT2 66   // sg stride in float2

// ---------------------------------------------------------------------------
// Packed f32x2 helpers (sm_103a). Lane0 = .x (even col), lane1 = .y.
// ---------------------------------------------------------------------------
typedef unsigned long long u64t;
__device__ __forceinline__ u64t pk2(float lo, float hi) {
    u64t r; asm("mov.b64 %0,{%1,%2};" : "=l"(r) : "f"(lo), "f"(hi)); return r;
}
__device__ __forceinline__ void upk2(u64t v, float& lo, float& hi) {
    asm("mov.b64 {%0,%1},%2;" : "=f"(lo), "=f"(hi) : "l"(v));
}
__device__ __forceinline__ u64t add2(u64t a, u64t b) {
    u64t r; asm("add.rn.f32x2 %0,%1,%2;" : "=l"(r) : "l"(a), "l"(b)); return r;
}
__device__ __forceinline__ u64t mul2(u64t a, u64t b) {
    u64t r; asm("mul.rn.f32x2 %0,%1,%2;" : "=l"(r) : "l"(a), "l"(b)); return r;
}
__device__ __forceinline__ u64t fma2(u64t a, u64t b, u64t c) {
    u64t r; asm("fma.rn.f32x2 %0,%1,%2,%3;" : "=l"(r) : "l"(a), "l"(b), "l"(c)); return r;
}

// ---------------------------------------------------------------------------
// Generic (border-correct) Hessian from a smem tile.
// jnp.gradient semantics: central interior, one-sided edges, applied twice.
// ---------------------------------------------------------------------------
__device__ __forceinline__ float gHs(const float* s, int st, int li, int lj, int gi) {
    if (gi == 0)      return s[(li + 1) * st + lj] - s[li * st + lj];
    if (gi == Hd - 1) return s[li * st + lj] - s[(li - 1) * st + lj];
    return 0.5f * (s[(li + 1) * st + lj] - s[(li - 1) * st + lj]);
}
__device__ __forceinline__ float gWs(const float* s, int st, int li, int lj, int gj) {
    if (gj == 0)      return s[li * st + lj + 1] - s[li * st + lj];
    if (gj == Wd - 1) return s[li * st + lj] - s[li * st + lj - 1];
    return 0.5f * (s[li * st + lj + 1] - s[li * st + lj - 1]);
}
__device__ __forceinline__ void hess_g(const float* s, int st, int li, int lj,
                                       int gi, int gj,
                                       float& h00, float& h01, float& h11) {
    if (gi == 0)           h00 = gHs(s, st, li + 1, lj, 1) - gHs(s, st, li, lj, 0);
    else if (gi == Hd - 1) h00 = gHs(s, st, li, lj, Hd - 1) - gHs(s, st, li - 1, lj, Hd - 2);
    else                   h00 = 0.5f * (gHs(s, st, li + 1, lj, gi + 1) - gHs(s, st, li - 1, lj, gi - 1));
    if (gj == 0)           h01 = gHs(s, st, li, lj + 1, gi) - gHs(s, st, li, lj, gi);
    else if (gj == Wd - 1) h01 = gHs(s, st, li, lj, gi) - gHs(s, st, li, lj - 1, gi);
    else                   h01 = 0.5f * (gHs(s, st, li, lj + 1, gi) - gHs(s, st, li, lj - 1, gi));
    if (gj == 0)           h11 = gWs(s, st, li, lj + 1, 1) - gWs(s, st, li, lj, 0);
    else if (gj == Wd - 1) h11 = gWs(s, st, li, lj, Wd - 1) - gWs(s, st, li, lj - 1, Wd - 2);
    else                   h11 = 0.5f * (gWs(s, st, li, lj + 1, gj + 1) - gWs(s, st, li, lj - 1, gj - 1));
}

__device__ __forceinline__ float eig_store(float mean, float d2, float s2,
                                           __half2* tsp) {
    float disc = sqrtf(d2);
    float am = fabsf(mean);
    float lam2 = fmaxf(copysignf(am + disc, mean), 1e-10f);
    float lam1a = fabsf(am - disc);
    float rb = __fdividef(lam1a, lam2);
    float t1 = __expf(-2.0f * rb * rb);
    *tsp = __floats2half2_rn(t1, s2);
    return s2;
}

// ---------------------------------------------------------------------------
// Interior pair path: thread owns cols (2*txp, 2*txp+1), 8 rows from r0.
// cq = txp: w[d][1] = center pair {lj0, lj0+1}, lj0 = 2*txp + 2.
// ---------------------------------------------------------------------------
__device__ __forceinline__ float ts_pair_run(const float* sg, __half2* tsp,
                                             int cq, int r0) {
    const float2* s2p_base = (const float2*)sg;  // sg 16B-aligned
    float m = 0.0f;
    float2 w[5][3];
#pragma unroll
    for (int d = 0; d < 5; d++) {
#pragma unroll
        for (int c = 0; c < 3; c++)
            w[d][c] = s2p_base[(size_t)(r0 + d) * SGT2 + cq + c];
    }
    const u64t kM1 = pk2(-1.0f, -1.0f);
    const u64t kM2 = pk2(-2.0f, -2.0f);
    const u64t k18 = pk2(0.125f, 0.125f);
    const u64t k14 = pk2(0.25f, 0.25f);
    const u64t kTwo = pk2(2.0f, 2.0f);
#pragma unroll
    for (int k = 0; k < 8; k++) {
        u64t c_m2 = *(const u64t*)&w[0][1];
        u64t c_0  = *(const u64t*)&w[2][1];
        u64t c_p2 = *(const u64t*)&w[4][1];
        u64t l_0  = *(const u64t*)&w[2][0];
        u64t r_0  = *(const u64t*)&w[2][2];
        u64t H00 = fma2(c_0, kM2, add2(c_m2, c_p2));          // 4*h00
        u64t H11 = fma2(c_0, kM2, add2(l_0, r_0));            // 4*h11
        u64t R1 = pk2(w[1][1].y, w[1][2].x);
        u64t L1 = pk2(w[1][0].y, w[1][1].x);
        u64t R3 = pk2(w[3][1].y, w[3][2].x);
        u64t L3 = pk2(w[3][0].y, w[3][1].x);
        u64t D3 = fma2(L3, kM1, R3);
        u64t D1 = fma2(L1, kM1, R1);
        u64t H01 = fma2(D1, kM1, D3);                          // 4*h01
        u64t meanp = mul2(add2(H00, H11), k18);
        u64t diffp = mul2(fma2(H11, kM1, H00), k18);
        u64t h01p  = mul2(H01, k14);
        u64t d2p = fma2(diffp, diffp, mul2(h01p, h01p));
        u64t s2p = mul2(fma2(meanp, meanp, d2p), kTwo);

        float ma, mb, da, db, sa, sb;
        upk2(meanp, ma, mb);
        upk2(d2p, da, db);
        upk2(s2p, sa, sb);
        __half2 ha, hb;
        {
            float disc = sqrtf(da);
            float am = fabsf(ma);
            float lam2v = fmaxf(copysignf(am + disc, ma), 1e-10f);
            float rb = __fdividef(fabsf(am - disc), lam2v);
            ha = __floats2half2_rn(__expf(-2.0f * rb * rb), sa);
        }
        {
            float disc = sqrtf(db);
            float am = fabsf(mb);
            float lam2v = fmaxf(copysignf(am + disc, mb), 1e-10f);
            float rb = __fdividef(fabsf(am - disc), lam2v);
            hb = __floats2half2_rn(__expf(-2.0f * rb * rb), sb);
        }
        *(uint2*)tsp = make_uint2(*(unsigned int*)&ha, *(unsigned int*)&hb);
        m = fmaxf(m, fmaxf(sa, sb));
        tsp += Wd;
        if (k < 7) {
#pragma unroll
            for (int d = 0; d < 4; d++) {
                w[d][0] = w[d + 1][0]; w[d][1] = w[d + 1][1]; w[d][2] = w[d + 1][2];
            }
#pragma unroll
            for (int c = 0; c < 3; c++)
                w[4][c] = s2p_base[(size_t)(r0 + k + 5) * SGT2 + cq + c];
        }
    }
    return m;
}

// Border path: fully scalar, per-pixel generic/interior selection (rare).
__device__ __forceinline__ float ts_border_run(const float* sg, __half2* tsp0,
                                               int txp, int r0, int i0, int j0) {
    float m = 0.0f;
#pragma unroll
    for (int c = 0; c < 2; c++) {
        int lj = 2 * txp + c + 2;
        int gj = j0 + 2 * txp + c;
        __half2* tsp = tsp0 + c;
        for (int k = 0; k < 8; k++) {
            int gi = i0 + r0 + k;
            int li = r0 + k + 2;
            float h00, h01, h11;
            if ((gj < 2) | (gj >= Wd - 2) | (gi < 2) | (gi >= Hd - 2)) {
                hess_g(sg, SGT, li, lj, gi, gj, h00, h01, h11);
            } else {
                const float* pc = sg + li * SGT + lj;
                h00 = 0.25f * (pc[2 * SGT] - 2.0f * pc[0] + pc[-2 * SGT]);
                h01 = 0.25f * ((pc[SGT + 1] - pc[-SGT + 1]) - (pc[SGT - 1] - pc[-SGT - 1]));
                h11 = 0.25f * (pc[-2] - 2.0f * pc[0] + pc[2]);
            }
            float mean = 0.5f * (h00 + h11);
            float diff = 0.5f * (h00 - h11);
            float d2 = diff * diff + h01 * h01;
            float s2 = 2.0f * (mean * mean + d2);
            m = fmaxf(m, eig_store(mean, d2, s2, tsp));
            tsp += Wd;
        }
    }
    return m;
}

// ---------------------------------------------------------------------------
// K1: grayscale + separable 5x5 blur + Hessian -> packed {t1, s2} + max(s^2).
// Tile 128x64, 512 threads, dynamic smem: sgray[72][136] then sg[68][132]
// overlay; shb[72][132].
// ---------------------------------------------------------------------------
__global__ void __launch_bounds__(512, 2) k_grayblur_ts(
        const float* __restrict__ x, const float* __restrict__ to_gray) {
    extern __shared__ __align__(16) float buf[];
    float* sgray = buf;              // [72][136]
    float* shb   = buf + 72 * SGS;   // [72][132]
    float* sg    = buf;              // [68][132] overlays sgray

    const int b  = blockIdx.z;
    const int i0 = blockIdx.y * 64;
    const int j0 = blockIdx.x * 128;
    const int t  = threadIdx.x;

    const float c0 = to_gray[0], c1 = to_gray[1], c2 = to_gray[2];
    const float* __restrict__ xr = x + (size_t)b * 3 * Hd * Wd;
    const float* __restrict__ xg = xr + (size_t)Hd * Wd;
    const float* __restrict__ xb = xg + (size_t)Hd * Wd;

    // Gray load: 72 rows x 34 float4-quads (halo 4). Interior blocks skip checks.
    const bool interior = (blockIdx.x > 0) & (blockIdx.x < gridDim.x - 1) &
                          (blockIdx.y > 0) & (blockIdx.y < gridDim.y - 1);
    if (interior) {
        for (int idx = t; idx < 72 * 34; idx += 512) {
            int li = idx / 34, q = idx - li * 34;
            size_t o = (size_t)(i0 + li - 4) * Wd + (j0 + q * 4 - 4);
            float4 r = *(const float4*)(xr + o);
            float4 g = *(const float4*)(xg + o);
            float4 bb = *(const float4*)(xb + o);
            float4 v;
            v.x = c0 * r.x + c1 * g.x + c2 * bb.x;
            v.y = c0 * r.y + c1 * g.y + c2 * bb.y;
            v.z = c0 * r.z + c1 * g.z + c2 * bb.z;
            v.w = c0 * r.w + c1 * g.w + c2 * bb.w;
            *(float4*)&sgray[li * SGS + q * 4] = v;
        }
    } else {
        for (int idx = t; idx < 72 * 34; idx += 512) {
            int li = idx / 34, q = idx - li * 34;
            int gi = i0 + li - 4, gjq = j0 + q * 4 - 4;
            float4 v = make_float4(0.f, 0.f, 0.f, 0.f);
            if ((unsigned)gi < Hd && (unsigned)gjq < Wd) {
                size_t o = (size_t)gi * Wd + gjq;
                float4 r = *(const float4*)(xr + o);
                float4 g = *(const float4*)(xg + o);
                float4 bb = *(const float4*)(xb + o);
                v.x = c0 * r.x + c1 * g.x + c2 * bb.x;
                v.y = c0 * r.y + c1 * g.y + c2 * bb.y;
                v.z = c0 * r.z + c1 * g.z + c2 * bb.z;
                v.w = c0 * r.w + c1 * g.w + c2 * bb.w;
            }
            *(float4*)&sgray[li * SGS + q * 4] = v;
        }
    }
    __syncthreads();

    // Horizontal 5-tap: 72 rows x 33 quads (out cols 0..131)
    for (int idx = t; idx < 72 * 33; idx += 512) {
        int li = idx / 33, q = idx - li * 33;
        const float* r = &sgray[li * SGS + q * 4];
        float4 A = *(const float4*)r;
        float4 B = *(const float4*)(r + 4);
        float4 o;
        o.x = W0 * (A.x + B.x) + W1 * (A.y + A.w) + W2 * A.z;
        o.y = W0 * (A.y + B.y) + W1 * (A.z + B.x) + W2 * A.w;
        o.z = W0 * (A.z + B.z) + W1 * (A.w + B.y) + W2 * B.x;
        o.w = W0 * (A.w + B.w) + W1 * (B.x + B.z) + W2 * B.y;
        *(float4*)&shb[li * SHS + q * 4] = o;
    }
    __syncthreads();

    // Vertical 5-tap: 17 row-quads x 132 cols -> sg (overlays dead sgray)
    for (int idx = t; idx < 17 * 132; idx += 512) {
        int rq = idx / 132, lj = idx - rq * 132;
        const float* p = &shb[rq * 4 * SHS + lj];
        float a0 = p[0], a1 = p[SHS], a2 = p[2 * SHS], a3 = p[3 * SHS];
        float a4 = p[4 * SHS], a5 = p[5 * SHS], a6 = p[6 * SHS], a7 = p[7 * SHS];
        float* o = &sg[rq * 4 * SGT + lj];
        o[0]       = W0 * (a0 + a4) + W1 * (a1 + a3) + W2 * a2;
        o[SGT]     = W0 * (a1 + a5) + W1 * (a2 + a4) + W2 * a3;
        o[2 * SGT] = W0 * (a2 + a6) + W1 * (a3 + a5) + W2 * a4;
        o[3 * SGT] = W0 * (a3 + a7) + W1 * (a4 + a6) + W2 * a5;
    }
    __syncthreads();

    // Hessian -> packed {t1, s2} + max(s2): thread owns col-pair txp, 8 rows.
    int txp = t & 63, ty = t >> 6;
    int r0 = ty * 8;
    int gj0 = j0 + 2 * txp;
    __half2* tsp = d_ts + ((size_t)b * Hd + (i0 + r0)) * Wd + gj0;
    bool jb = (gj0 < 2) | (gj0 + 1 >= Wd - 2);
    bool rowborder = (i0 == 0) | (i0 + 64 == Hd);
    float m;
    if (jb | rowborder)
        m = ts_border_run(sg, tsp, txp, r0, i0, j0);
    else
        m = ts_pair_run(sg, tsp, txp, r0);

#pragma unroll
    for (int o = 16; o > 0; o >>= 1)
        m = fmaxf(m, __shfl_xor_sync(0xffffffffu, m, o));
    __shared__ float wm[16];
    __shared__ int sflag;
    int lane = t & 31, wid = t >> 5;
    if (lane == 0) wm[wid] = m;
    __syncthreads();
    if (t == 0) {
        m = wm[0];
#pragma unroll
        for (int i = 1; i < 16; i++) m = fmaxf(m, wm[i]);
        d_blockmax[(b << 7) | (blockIdx.y << 3) | blockIdx.x] = m;
        __threadfence();
        unsigned int c = atomicAdd(&d_counter, 1u);
        sflag = (c == (unsigned)(Bd * 128 - 1));
    }
    __syncthreads();

    if (sflag) {  // last-finishing block computes gamma (self-reset counter)
        __shared__ float sbm[Bd];
        if (wid < Bd) {
            float m2 = 0.0f;
#pragma unroll
            for (int i = 0; i < 4; i++)
                m2 = fmaxf(m2, d_blockmax[(wid << 7) | (i * 32 + lane)]);
#pragma unroll
            for (int o = 16; o > 0; o >>= 1)
                m2 = fmaxf(m2, __shfl_xor_sync(0xffffffffu, m2, o));
            if (lane == 0) sbm[wid] = m2;
        }
        __syncthreads();
        if (t == 0) {
            float orall = 0.0f;
#pragma unroll
            for (int i = 0; i < Bd; i++) orall = fmaxf(orall, sbm[i]);
#pragma unroll
            for (int i = 0; i < Bd; i++) {
                float gm = (orall == 0.0f) ? 1.0f : 0.5f * sqrtf(sbm[i]);
                d_inv2g2[i] = 1.0f / (2.0f * gm * gm);
            }
            d_counter = 0;  // deterministic across graph replays
        }
    }
}

// ---------------------------------------------------------------------------
// K2: final elementwise response. 8 px/thread = 2 uint4 loads + 2 float4 stores.
// ---------------------------------------------------------------------------
__device__ __forceinline__ float fin1(float t1, float s2, float inv) {
    float vals = t1 * (1.0f - __expf(-s2 * inv));
    float f = fmaxf(0.0f, vals);
    return (f <= 0.0f) ? 1.0f : f;
}
__device__ __forceinline__ float4 fin4(uint4 raw, float inv) {
    float2 p0 = __half22float2(*reinterpret_cast<const __half2*>(&raw.x));
    float2 p1 = __half22float2(*reinterpret_cast<const __half2*>(&raw.y));
    float2 p2 = __half22float2(*reinterpret_cast<const __half2*>(&raw.z));
    float2 p3 = __half22float2(*reinterpret_cast<const __half2*>(&raw.w));
    float4 o;
    o.x = fin1(p0.x, p0.y, inv);
    o.y = fin1(p1.x, p1.y, inv);
    o.z = fin1(p2.x, p2.y, inv);
    o.w = fin1(p3.x, p3.y, inv);
    return o;
}

__global__ void __launch_bounds__(256) k_final(float* __restrict__ out) {
    const size_t i8 = (size_t)blockIdx.x * 256 + threadIdx.x;  // 8-px group
    const float inv = d_inv2g2[blockIdx.x >> 9];               // 512 blk/image

    const uint4* tp = (const uint4*)d_ts + i8 * 2;
    uint4 ra = tp[0];
    uint4 rb = tp[1];
    float4* op = (float4*)out + i8 * 2;
    op[0] = fin4(ra, inv);
    op[1] = fin4(rb, inv);
}

// ---------------------------------------------------------------------------
extern "C" void kernel_launch(void* const* d_in, const int* in_sizes, int n_in,
                              void* d_out, int out_size) {
    const float* x  = (const float*)d_in[0];
    const float* tg = (const float*)d_in[1];
    if (n_in >= 2 && in_sizes[0] == 3) {  // defensive: order per metadata
        const float* tmp = x; x = tg; tg = tmp;
    }
    float* out = (float*)d_out;

    const int smem = (72 * SGS + 72 * SHS) * 4;  // 77184 B
    cudaFuncSetAttribute(k_grayblur_ts,
                         cudaFuncAttributeMaxDynamicSharedMemorySize, smem);
    k_grayblur_ts<<<dim3(Wd / 128, Hd / 64, Bd), 512, smem>>>(x, tg);
    k_final<<<(Bd * Hd * Wd) / (256 * 8), 256>>>(out);
}

// round 14
// speedup vs baseline: 1.0009x; 1.0009x over previous
#include <cuda_runtime.h>
#include <cuda_fp16.h>

#define Hd 1024
#define Wd 1024
#define Bd 16

// Scratch: per-pixel packed {t1 = exp(-2 rb^2), s2} as half2 (4B/px);
// per-block s2 maxima; completion counter; per-batch 1/(2*gamma^2).
__device__ __half2 d_ts[(size_t)Bd * Hd * Wd];
__device__ float d_blockmax[Bd * 128];
__device__ unsigned int d_counter = 0;
__device__ float d_inv2g2[Bd];

// Separable 1D Gaussian weights (outer(w,w) == gaussian_kernel(5,10)).
#define W0 0.19800304f
#define W1 0.20099548f
#define W2 0.20200297f

// Tile geometry: 128 wide x 64 tall, halo 4.
#define SGS 136   // sgray stride (floats), 72 rows
#define SHS 132   // shb stride, 72 rows (cols 0..131)
#define SGT 132   // sg stride, 68 rows (overlays sgray)
#define SGT2 66   // sg stride in float2

// ---------------------------------------------------------------------------
// Packed f32x2 helpers (sm_103a). Lane0 = .x (even col), lane1 = .y.
// ---------------------------------------------------------------------------
typedef unsigned long long u64t;
__device__ __forceinline__ u64t pk2(float lo, float hi) {
    u64t r; asm("mov.b64 %0,{%1,%2};" : "=l"(r) : "f"(lo), "f"(hi)); return r;
}
__device__ __forceinline__ void upk2(u64t v, float& lo, float& hi) {
    asm("mov.b64 {%0,%1},%2;" : "=f"(lo), "=f"(hi) : "l"(v));
}
__device__ __forceinline__ u64t add2(u64t a, u64t b) {
    u64t r; asm("add.rn.f32x2 %0,%1,%2;" : "=l"(r) : "l"(a), "l"(b)); return r;
}
__device__ __forceinline__ u64t mul2(u64t a, u64t b) {
    u64t r; asm("mul.rn.f32x2 %0,%1,%2;" : "=l"(r) : "l"(a), "l"(b)); return r;
}
__device__ __forceinline__ u64t fma2(u64t a, u64t b, u64t c) {
    u64t r; asm("fma.rn.f32x2 %0,%1,%2,%3;" : "=l"(r) : "l"(a), "l"(b), "l"(c)); return r;
}

// ---------------------------------------------------------------------------
// Generic (border-correct) Hessian from a smem tile.
// jnp.gradient semantics: central interior, one-sided edges, applied twice.
// ---------------------------------------------------------------------------
__device__ __forceinline__ float gHs(const float* s, int st, int li, int lj, int gi) {
    if (gi == 0)      return s[(li + 1) * st + lj] - s[li * st + lj];
    if (gi == Hd - 1) return s[li * st + lj] - s[(li - 1) * st + lj];
    return 0.5f * (s[(li + 1) * st + lj] - s[(li - 1) * st + lj]);
}
__device__ __forceinline__ float gWs(const float* s, int st, int li, int lj, int gj) {
    if (gj == 0)      return s[li * st + lj + 1] - s[li * st + lj];
    if (gj == Wd - 1) return s[li * st + lj] - s[li * st + lj - 1];
    return 0.5f * (s[li * st + lj + 1] - s[li * st + lj - 1]);
}
__device__ __forceinline__ void hess_g(const float* s, int st, int li, int lj,
                                       int gi, int gj,
                                       float& h00, float& h01, float& h11) {
    if (gi == 0)           h00 = gHs(s, st, li + 1, lj, 1) - gHs(s, st, li, lj, 0);
    else if (gi == Hd - 1) h00 = gHs(s, st, li, lj, Hd - 1) - gHs(s, st, li - 1, lj, Hd - 2);
    else                   h00 = 0.5f * (gHs(s, st, li + 1, lj, gi + 1) - gHs(s, st, li - 1, lj, gi - 1));
    if (gj == 0)           h01 = gHs(s, st, li, lj + 1, gi) - gHs(s, st, li, lj, gi);
    else if (gj == Wd - 1) h01 = gHs(s, st, li, lj, gi) - gHs(s, st, li, lj - 1, gi);
    else                   h01 = 0.5f * (gHs(s, st, li, lj + 1, gi) - gHs(s, st, li, lj - 1, gi));
    if (gj == 0)           h11 = gWs(s, st, li, lj + 1, 1) - gWs(s, st, li, lj, 0);
    else if (gj == Wd - 1) h11 = gWs(s, st, li, lj, Wd - 1) - gWs(s, st, li, lj - 1, Wd - 2);
    else                   h11 = 0.5f * (gWs(s, st, li, lj + 1, gj + 1) - gWs(s, st, li, lj - 1, gj - 1));
}

__device__ __forceinline__ float eig_store(float mean, float d2, float s2,
                                           __half2* tsp) {
    float disc = sqrtf(d2);
    float am = fabsf(mean);
    float lam2 = fmaxf(copysignf(am + disc, mean), 1e-10f);
    float lam1a = fabsf(am - disc);
    float rb = __fdividef(lam1a, lam2);
    float t1 = __expf(-2.0f * rb * rb);
    *tsp = __floats2half2_rn(t1, s2);
    return s2;
}

// ---------------------------------------------------------------------------
// Interior pair path: thread owns cols (2*txp, 2*txp+1), 8 rows from r0.
// cq = txp: w[d][1] = center pair {lj0, lj0+1}, lj0 = 2*txp + 2.
// ---------------------------------------------------------------------------
__device__ __forceinline__ float ts_pair_run(const float* sg, __half2* tsp,
                                             int cq, int r0) {
    const float2* s2p_base = (const float2*)sg;  // sg 16B-aligned
    float m = 0.0f;
    float2 w[5][3];
#pragma unroll
    for (int d = 0; d < 5; d++) {
#pragma unroll
        for (int c = 0; c < 3; c++)
            w[d][c] = s2p_base[(size_t)(r0 + d) * SGT2 + cq + c];
    }
    const u64t kM1 = pk2(-1.0f, -1.0f);
    const u64t kM2 = pk2(-2.0f, -2.0f);
    const u64t k18 = pk2(0.125f, 0.125f);
    const u64t k14 = pk2(0.25f, 0.25f);
    const u64t kTwo = pk2(2.0f, 2.0f);
#pragma unroll
    for (int k = 0; k < 8; k++) {
        u64t c_m2 = *(const u64t*)&w[0][1];
        u64t c_0  = *(const u64t*)&w[2][1];
        u64t c_p2 = *(const u64t*)&w[4][1];
        u64t l_0  = *(const u64t*)&w[2][0];
        u64t r_0  = *(const u64t*)&w[2][2];
        u64t H00 = fma2(c_0, kM2, add2(c_m2, c_p2));          // 4*h00
        u64t H11 = fma2(c_0, kM2, add2(l_0, r_0));            // 4*h11
        u64t R1 = pk2(w[1][1].y, w[1][2].x);
        u64t L1 = pk2(w[1][0].y, w[1][1].x);
        u64t R3 = pk2(w[3][1].y, w[3][2].x);
        u64t L3 = pk2(w[3][0].y, w[3][1].x);
        u64t D3 = fma2(L3, kM1, R3);
        u64t D1 = fma2(L1, kM1, R1);
        u64t H01 = fma2(D1, kM1, D3);                          // 4*h01
        u64t meanp = mul2(add2(H00, H11), k18);
        u64t diffp = mul2(fma2(H11, kM1, H00), k18);
        u64t h01p  = mul2(H01, k14);
        u64t d2p = fma2(diffp, diffp, mul2(h01p, h01p));
        u64t s2p = mul2(fma2(meanp, meanp, d2p), kTwo);

        float ma, mb, da, db, sa, sb;
        upk2(meanp, ma, mb);
        upk2(d2p, da, db);
        upk2(s2p, sa, sb);
        __half2 ha, hb;
        {
            float disc = sqrtf(da);
            float am = fabsf(ma);
            float lam2v = fmaxf(copysignf(am + disc, ma), 1e-10f);
            float rb = __fdividef(fabsf(am - disc), lam2v);
            ha = __floats2half2_rn(__expf(-2.0f * rb * rb), sa);
        }
        {
            float disc = sqrtf(db);
            float am = fabsf(mb);
            float lam2v = fmaxf(copysignf(am + disc, mb), 1e-10f);
            float rb = __fdividef(fabsf(am - disc), lam2v);
            hb = __floats2half2_rn(__expf(-2.0f * rb * rb), sb);
        }
        *(uint2*)tsp = make_uint2(*(unsigned int*)&ha, *(unsigned int*)&hb);
        m = fmaxf(m, fmaxf(sa, sb));
        tsp += Wd;
        if (k < 7) {
#pragma unroll
            for (int d = 0; d < 4; d++) {
                w[d][0] = w[d + 1][0]; w[d][1] = w[d + 1][1]; w[d][2] = w[d + 1][2];
            }
#pragma unroll
            for (int c = 0; c < 3; c++)
                w[4][c] = s2p_base[(size_t)(r0 + k + 5) * SGT2 + cq + c];
        }
    }
    return m;
}

// Border path: fully scalar, per-pixel generic/interior selection (rare).
__device__ __forceinline__ float ts_border_run(const float* sg, __half2* tsp0,
                                               int txp, int r0, int i0, int j0) {
    float m = 0.0f;
#pragma unroll
    for (int c = 0; c < 2; c++) {
        int lj = 2 * txp + c + 2;
        int gj = j0 + 2 * txp + c;
        __half2* tsp = tsp0 + c;
        for (int k = 0; k < 8; k++) {
            int gi = i0 + r0 + k;
            int li = r0 + k + 2;
            float h00, h01, h11;
            if ((gj < 2) | (gj >= Wd - 2) | (gi < 2) | (gi >= Hd - 2)) {
                hess_g(sg, SGT, li, lj, gi, gj, h00, h01, h11);
            } else {
                const float* pc = sg + li * SGT + lj;
                h00 = 0.25f * (pc[2 * SGT] - 2.0f * pc[0] + pc[-2 * SGT]);
                h01 = 0.25f * ((pc[SGT + 1] - pc[-SGT + 1]) - (pc[SGT - 1] - pc[-SGT - 1]));
                h11 = 0.25f * (pc[-2] - 2.0f * pc[0] + pc[2]);
            }
            float mean = 0.5f * (h00 + h11);
            float diff = 0.5f * (h00 - h11);
            float d2 = diff * diff + h01 * h01;
            float s2 = 2.0f * (mean * mean + d2);
            m = fmaxf(m, eig_store(mean, d2, s2, tsp));
            tsp += Wd;
        }
    }
    return m;
}

// ---------------------------------------------------------------------------
// K1: grayscale + separable 5x5 blur + Hessian -> packed {t1, s2} + max(s^2).
// Tile 128x64, 512 threads, dynamic smem: sgray[72][136] then sg[68][132]
// overlay; shb[72][132].
// ---------------------------------------------------------------------------
__global__ void __launch_bounds__(512, 2) k_grayblur_ts(
        const float* __restrict__ x, const float* __restrict__ to_gray) {
    extern __shared__ __align__(16) float buf[];
    float* sgray = buf;              // [72][136]
    float* shb   = buf + 72 * SGS;   // [72][132]
    float* sg    = buf;              // [68][132] overlays sgray

    const int b  = blockIdx.z;
    const int i0 = blockIdx.y * 64;
    const int j0 = blockIdx.x * 128;
    const int t  = threadIdx.x;

    const float c0 = to_gray[0], c1 = to_gray[1], c2 = to_gray[2];
    const float* __restrict__ xr = x + (size_t)b * 3 * Hd * Wd;
    const float* __restrict__ xg = xr + (size_t)Hd * Wd;
    const float* __restrict__ xb = xg + (size_t)Hd * Wd;

    // Gray load: 72 rows x 34 float4-quads (halo 4). Interior blocks skip checks.
    const bool interior = (blockIdx.x > 0) & (blockIdx.x < gridDim.x - 1) &
                          (blockIdx.y > 0) & (blockIdx.y < gridDim.y - 1);
    if (interior) {
        for (int idx = t; idx < 72 * 34; idx += 512) {
            int li = idx / 34, q = idx - li * 34;
            size_t o = (size_t)(i0 + li - 4) * Wd + (j0 + q * 4 - 4);
            float4 r = *(const float4*)(xr + o);
            float4 g = *(const float4*)(xg + o);
            float4 bb = *(const float4*)(xb + o);
            float4 v;
            v.x = c0 * r.x + c1 * g.x + c2 * bb.x;
            v.y = c0 * r.y + c1 * g.y + c2 * bb.y;
            v.z = c0 * r.z + c1 * g.z + c2 * bb.z;
            v.w = c0 * r.w + c1 * g.w + c2 * bb.w;
            *(float4*)&sgray[li * SGS + q * 4] = v;
        }
    } else {
        for (int idx = t; idx < 72 * 34; idx += 512) {
            int li = idx / 34, q = idx - li * 34;
            int gi = i0 + li - 4, gjq = j0 + q * 4 - 4;
            float4 v = make_float4(0.f, 0.f, 0.f, 0.f);
            if ((unsigned)gi < Hd && (unsigned)gjq < Wd) {
                size_t o = (size_t)gi * Wd + gjq;
                float4 r = *(const float4*)(xr + o);
                float4 g = *(const float4*)(xg + o);
                float4 bb = *(const float4*)(xb + o);
                v.x = c0 * r.x + c1 * g.x + c2 * bb.x;
                v.y = c0 * r.y + c1 * g.y + c2 * bb.y;
                v.z = c0 * r.z + c1 * g.z + c2 * bb.z;
                v.w = c0 * r.w + c1 * g.w + c2 * bb.w;
            }
            *(float4*)&sgray[li * SGS + q * 4] = v;
        }
    }
    __syncthreads();

    // Horizontal 5-tap: 72 rows x 33 quads (out cols 0..131)
    for (int idx = t; idx < 72 * 33; idx += 512) {
        int li = idx / 33, q = idx - li * 33;
        const float* r = &sgray[li * SGS + q * 4];
        float4 A = *(const float4*)r;
        float4 B = *(const float4*)(r + 4);
        float4 o;
        o.x = W0 * (A.x + B.x) + W1 * (A.y + A.w) + W2 * A.z;
        o.y = W0 * (A.y + B.y) + W1 * (A.z + B.x) + W2 * A.w;
        o.z = W0 * (A.z + B.z) + W1 * (A.w + B.y) + W2 * B.x;
        o.w = W0 * (A.w + B.w) + W1 * (B.x + B.z) + W2 * B.y;
        *(float4*)&shb[li * SHS + q * 4] = o;
    }
    __syncthreads();

    // Vertical 5-tap: 17 row-quads x 132 cols -> sg (overlays dead sgray)
    for (int idx = t; idx < 17 * 132; idx += 512) {
        int rq = idx / 132, lj = idx - rq * 132;
        const float* p = &shb[rq * 4 * SHS + lj];
        float a0 = p[0], a1 = p[SHS], a2 = p[2 * SHS], a3 = p[3 * SHS];
        float a4 = p[4 * SHS], a5 = p[5 * SHS], a6 = p[6 * SHS], a7 = p[7 * SHS];
        float* o = &sg[rq * 4 * SGT + lj];
        o[0]       = W0 * (a0 + a4) + W1 * (a1 + a3) + W2 * a2;
        o[SGT]     = W0 * (a1 + a5) + W1 * (a2 + a4) + W2 * a3;
        o[2 * SGT] = W0 * (a2 + a6) + W1 * (a3 + a5) + W2 * a4;
        o[3 * SGT] = W0 * (a3 + a7) + W1 * (a4 + a6) + W2 * a5;
    }
    __syncthreads();

    // Hessian -> packed {t1, s2} + max(s2): thread owns col-pair txp, 8 rows.
    int txp = t & 63, ty = t >> 6;
    int r0 = ty * 8;
    int gj0 = j0 + 2 * txp;
    __half2* tsp = d_ts + ((size_t)b * Hd + (i0 + r0)) * Wd + gj0;
    bool jb = (gj0 < 2) | (gj0 + 1 >= Wd - 2);
    bool rowborder = (i0 == 0) | (i0 + 64 == Hd);
    float m;
    if (jb | rowborder)
        m = ts_border_run(sg, tsp, txp, r0, i0, j0);
    else
        m = ts_pair_run(sg, tsp, txp, r0);

#pragma unroll
    for (int o = 16; o > 0; o >>= 1)
        m = fmaxf(m, __shfl_xor_sync(0xffffffffu, m, o));
    __shared__ float wm[16];
    __shared__ int sflag;
    int lane = t & 31, wid = t >> 5;
    if (lane == 0) wm[wid] = m;
    __syncthreads();
    if (t == 0) {
        m = wm[0];
#pragma unroll
        for (int i = 1; i < 16; i++) m = fmaxf(m, wm[i]);
        d_blockmax[(b << 7) | (blockIdx.y << 3) | blockIdx.x] = m;
        __threadfence();
        unsigned int c = atomicAdd(&d_counter, 1u);
        sflag = (c == (unsigned)(Bd * 128 - 1));
    }
    __syncthreads();

    if (sflag) {  // last-finishing block computes gamma (self-reset counter)
        __shared__ float sbm[Bd];
        if (wid < Bd) {
            float m2 = 0.0f;
#pragma unroll
            for (int i = 0; i < 4; i++)
                m2 = fmaxf(m2, d_blockmax[(wid << 7) | (i * 32 + lane)]);
#pragma unroll
            for (int o = 16; o > 0; o >>= 1)
                m2 = fmaxf(m2, __shfl_xor_sync(0xffffffffu, m2, o));
            if (lane == 0) sbm[wid] = m2;
        }
        __syncthreads();
        if (t == 0) {
            float orall = 0.0f;
#pragma unroll
            for (int i = 0; i < Bd; i++) orall = fmaxf(orall, sbm[i]);
#pragma unroll
            for (int i = 0; i < Bd; i++) {
                float gm = (orall == 0.0f) ? 1.0f : 0.5f * sqrtf(sbm[i]);
                d_inv2g2[i] = 1.0f / (2.0f * gm * gm);
            }
            d_counter = 0;  // deterministic across graph replays
        }
    }
}

// ---------------------------------------------------------------------------
// K2: final elementwise response. 8 px/thread = 2 uint4 loads + 2 float4 stores.
// ---------------------------------------------------------------------------
__device__ __forceinline__ float fin1(float t1, float s2, float inv) {
    float vals = t1 * (1.0f - __expf(-s2 * inv));
    float f = fmaxf(0.0f, vals);
    return (f <= 0.0f) ? 1.0f : f;
}
__device__ __forceinline__ float4 fin4(uint4 raw, float inv) {
    float2 p0 = __half22float2(*reinterpret_cast<const __half2*>(&raw.x));
    float2 p1 = __half22float2(*reinterpret_cast<const __half2*>(&raw.y));
    float2 p2 = __half22float2(*reinterpret_cast<const __half2*>(&raw.z));
    float2 p3 = __half22float2(*reinterpret_cast<const __half2*>(&raw.w));
    float4 o;
    o.x = fin1(p0.x, p0.y, inv);
    o.y = fin1(p1.x, p1.y, inv);
    o.z = fin1(p2.x, p2.y, inv);
    o.w = fin1(p3.x, p3.y, inv);
    return o;
}

__global__ void __launch_bounds__(256) k_final(float* __restrict__ out) {
    const size_t i8 = (size_t)blockIdx.x * 256 + threadIdx.x;  // 8-px group
    const float inv = d_inv2g2[blockIdx.x >> 9];               // 512 blk/image

    const uint4* tp = (const uint4*)d_ts + i8 * 2;
    uint4 ra = tp[0];
    uint4 rb = tp[1];
    float4* op = (float4*)out + i8 * 2;
    op[0] = fin4(ra, inv);
    op[1] = fin4(rb, inv);
}

// ---------------------------------------------------------------------------
extern "C" void kernel_launch(void* const* d_in, const int* in_sizes, int n_in,
                              void* d_out, int out_size) {
    const float* x  = (const float*)d_in[0];
    const float* tg = (const float*)d_in[1];
    if (n_in >= 2 && in_sizes[0] == 3) {  // defensive: order per metadata
        const float* tmp = x; x = tg; tg = tmp;
    }
    float* out = (float*)d_out;

    const int smem = (72 * SGS + 72 * SHS) * 4;  // 77184 B
    cudaFuncSetAttribute(k_grayblur_ts,
                         cudaFuncAttributeMaxDynamicSharedMemorySize, smem);
    k_grayblur_ts<<<dim3(Wd / 128, Hd / 64, Bd), 512, smem>>>(x, tg);
    k_final<<<(Bd * Hd * Wd) / (256 * 8), 256>>>(out);
}

// round 15
// speedup vs baseline: 1.0032x; 1.0023x over previous
#include <cuda_runtime.h>
#include <cuda_fp16.h>

#define Hd 1024
#define Wd 1024
#define Bd 16

// Scratch: per-pixel packed {t1 = exp(-2 rb^2), s2} as half2 (4B/px);
// per-block s2 maxima; completion counter; per-batch 1/(2*gamma^2).
__device__ __half2 d_ts[(size_t)Bd * Hd * Wd];
__device__ float d_blockmax[Bd * 128];
__device__ unsigned int d_counter = 0;
__device__ float d_inv2g2[Bd];

// Separable 1D Gaussian weights (outer(w,w) == gaussian_kernel(5,10)).
#define W0 0.19800304f
#define W1 0.20099548f
#define W2 0.20200297f

// Tile geometry: 128 wide x 64 tall, halo 4.
#define SGS 136   // sgray stride (floats), 72 rows
#define SHS 132   // shb stride, 72 rows (cols 0..131)
#define SGT 132   // sg stride, 68 rows (overlays sgray)
#define SGT2 66   // sg stride in float2

// ---------------------------------------------------------------------------
// Packed f32x2 helpers (sm_103a). Lane0 = .x (even col), lane1 = .y.
// ---------------------------------------------------------------------------
typedef unsigned long long u64t;
__device__ __forceinline__ u64t pk2(float lo, float hi) {
    u64t r; asm("mov.b64 %0,{%1,%2};" : "=l"(r) : "f"(lo), "f"(hi)); return r;
}
__device__ __forceinline__ void upk2(u64t v, float& lo, float& hi) {
    asm("mov.b64 {%0,%1},%2;" : "=f"(lo), "=f"(hi) : "l"(v));
}
__device__ __forceinline__ u64t add2(u64t a, u64t b) {
    u64t r; asm("add.rn.f32x2 %0,%1,%2;" : "=l"(r) : "l"(a), "l"(b)); return r;
}
__device__ __forceinline__ u64t mul2(u64t a, u64t b) {
    u64t r; asm("mul.rn.f32x2 %0,%1,%2;" : "=l"(r) : "l"(a), "l"(b)); return r;
}
__device__ __forceinline__ u64t fma2(u64t a, u64t b, u64t c) {
    u64t r; asm("fma.rn.f32x2 %0,%1,%2,%3;" : "=l"(r) : "l"(a), "l"(b), "l"(c)); return r;
}

// ---------------------------------------------------------------------------
// Generic (border-correct) Hessian from a smem tile.
// jnp.gradient semantics: central interior, one-sided edges, applied twice.
// ---------------------------------------------------------------------------
__device__ __forceinline__ float gHs(const float* s, int st, int li, int lj, int gi) {
    if (gi == 0)      return s[(li + 1) * st + lj] - s[li * st + lj];
    if (gi == Hd - 1) return s[li * st + lj] - s[(li - 1) * st + lj];
    return 0.5f * (s[(li + 1) * st + lj] - s[(li - 1) * st + lj]);
}
__device__ __forceinline__ float gWs(const float* s, int st, int li, int lj, int gj) {
    if (gj == 0)      return s[li * st + lj + 1] - s[li * st + lj];
    if (gj == Wd - 1) return s[li * st + lj] - s[li * st + lj - 1];
    return 0.5f * (s[li * st + lj + 1] - s[li * st + lj - 1]);
}
__device__ __forceinline__ void hess_g(const float* s, int st, int li, int lj,
                                       int gi, int gj,
                                       float& h00, float& h01, float& h11) {
    if (gi == 0)           h00 = gHs(s, st, li + 1, lj, 1) - gHs(s, st, li, lj, 0);
    else if (gi == Hd - 1) h00 = gHs(s, st, li, lj, Hd - 1) - gHs(s, st, li - 1, lj, Hd - 2);
    else                   h00 = 0.5f * (gHs(s, st, li + 1, lj, gi + 1) - gHs(s, st, li - 1, lj, gi - 1));
    if (gj == 0)           h01 = gHs(s, st, li, lj + 1, gi) - gHs(s, st, li, lj, gi);
    else if (gj == Wd - 1) h01 = gHs(s, st, li, lj, gi) - gHs(s, st, li, lj - 1, gi);
    else                   h01 = 0.5f * (gHs(s, st, li, lj + 1, gi) - gHs(s, st, li, lj - 1, gi));
    if (gj == 0)           h11 = gWs(s, st, li, lj + 1, 1) - gWs(s, st, li, lj, 0);
    else if (gj == Wd - 1) h11 = gWs(s, st, li, lj, Wd - 1) - gWs(s, st, li, lj - 1, Wd - 2);
    else                   h11 = 0.5f * (gWs(s, st, li, lj + 1, gj + 1) - gWs(s, st, li, lj - 1, gj - 1));
}

__device__ __forceinline__ float eig_store(float mean, float d2, float s2,
                                           __half2* tsp) {
    float disc = sqrtf(d2);
    float am = fabsf(mean);
    float lam2 = fmaxf(copysignf(am + disc, mean), 1e-10f);
    float lam1a = fabsf(am - disc);
    float rb = __fdividef(lam1a, lam2);
    float t1 = __expf(-2.0f * rb * rb);
    *tsp = __floats2half2_rn(t1, s2);
    return s2;
}

// ---------------------------------------------------------------------------
// Interior pair path: thread owns cols (2*txp, 2*txp+1), 8 rows from r0.
// cq = txp: w[d][1] = center pair {lj0, lj0+1}, lj0 = 2*txp + 2.
// ---------------------------------------------------------------------------
__device__ __forceinline__ float ts_pair_run(const float* sg, __half2* tsp,
                                             int cq, int r0) {
    const float2* s2p_base = (const float2*)sg;  // sg 16B-aligned
    float m = 0.0f;
    float2 w[5][3];
#pragma unroll
    for (int d = 0; d < 5; d++) {
#pragma unroll
        for (int c = 0; c < 3; c++)
            w[d][c] = s2p_base[(size_t)(r0 + d) * SGT2 + cq + c];
    }
    const u64t kM1 = pk2(-1.0f, -1.0f);
    const u64t kM2 = pk2(-2.0f, -2.0f);
    const u64t k18 = pk2(0.125f, 0.125f);
    const u64t k14 = pk2(0.25f, 0.25f);
    const u64t kTwo = pk2(2.0f, 2.0f);
#pragma unroll
    for (int k = 0; k < 8; k++) {
        u64t c_m2 = *(const u64t*)&w[0][1];
        u64t c_0  = *(const u64t*)&w[2][1];
        u64t c_p2 = *(const u64t*)&w[4][1];
        u64t l_0  = *(const u64t*)&w[2][0];
        u64t r_0  = *(const u64t*)&w[2][2];
        u64t H00 = fma2(c_0, kM2, add2(c_m2, c_p2));          // 4*h00
        u64t H11 = fma2(c_0, kM2, add2(l_0, r_0));            // 4*h11
        u64t R1 = pk2(w[1][1].y, w[1][2].x);
        u64t L1 = pk2(w[1][0].y, w[1][1].x);
        u64t R3 = pk2(w[3][1].y, w[3][2].x);
        u64t L3 = pk2(w[3][0].y, w[3][1].x);
        u64t D3 = fma2(L3, kM1, R3);
        u64t D1 = fma2(L1, kM1, R1);
        u64t H01 = fma2(D1, kM1, D3);                          // 4*h01
        u64t meanp = mul2(add2(H00, H11), k18);
        u64t diffp = mul2(fma2(H11, kM1, H00), k18);
        u64t h01p  = mul2(H01, k14);
        u64t d2p = fma2(diffp, diffp, mul2(h01p, h01p));
        u64t s2p = mul2(fma2(meanp, meanp, d2p), kTwo);

        float ma, mb, da, db, sa, sb;
        upk2(meanp, ma, mb);
        upk2(d2p, da, db);
        upk2(s2p, sa, sb);
        __half2 ha, hb;
        {
            float disc = sqrtf(da);
            float am = fabsf(ma);
            float lam2v = fmaxf(copysignf(am + disc, ma), 1e-10f);
            float rb = __fdividef(fabsf(am - disc), lam2v);
            ha = __floats2half2_rn(__expf(-2.0f * rb * rb), sa);
        }
        {
            float disc = sqrtf(db);
            float am = fabsf(mb);
            float lam2v = fmaxf(copysignf(am + disc, mb), 1e-10f);
            float rb = __fdividef(fabsf(am - disc), lam2v);
            hb = __floats2half2_rn(__expf(-2.0f * rb * rb), sb);
        }
        *(uint2*)tsp = make_uint2(*(unsigned int*)&ha, *(unsigned int*)&hb);
        m = fmaxf(m, fmaxf(sa, sb));
        tsp += Wd;
        if (k < 7) {
#pragma unroll
            for (int d = 0; d < 4; d++) {
                w[d][0] = w[d + 1][0]; w[d][1] = w[d + 1][1]; w[d][2] = w[d + 1][2];
            }
#pragma unroll
            for (int c = 0; c < 3; c++)
                w[4][c] = s2p_base[(size_t)(r0 + k + 5) * SGT2 + cq + c];
        }
    }
    return m;
}

// Border path: fully scalar, per-pixel generic/interior selection (rare).
__device__ __forceinline__ float ts_border_run(const float* sg, __half2* tsp0,
                                               int txp, int r0, int i0, int j0) {
    float m = 0.0f;
#pragma unroll
    for (int c = 0; c < 2; c++) {
        int lj = 2 * txp + c + 2;
        int gj = j0 + 2 * txp + c;
        __half2* tsp = tsp0 + c;
        for (int k = 0; k < 8; k++) {
            int gi = i0 + r0 + k;
            int li = r0 + k + 2;
            float h00, h01, h11;
            if ((gj < 2) | (gj >= Wd - 2) | (gi < 2) | (gi >= Hd - 2)) {
                hess_g(sg, SGT, li, lj, gi, gj, h00, h01, h11);
            } else {
                const float* pc = sg + li * SGT + lj;
                h00 = 0.25f * (pc[2 * SGT] - 2.0f * pc[0] + pc[-2 * SGT]);
                h01 = 0.25f * ((pc[SGT + 1] - pc[-SGT + 1]) - (pc[SGT - 1] - pc[-SGT - 1]));
                h11 = 0.25f * (pc[-2] - 2.0f * pc[0] + pc[2]);
            }
            float mean = 0.5f * (h00 + h11);
            float diff = 0.5f * (h00 - h11);
            float d2 = diff * diff + h01 * h01;
            float s2 = 2.0f * (mean * mean + d2);
            m = fmaxf(m, eig_store(mean, d2, s2, tsp));
            tsp += Wd;
        }
    }
    return m;
}

// ---------------------------------------------------------------------------
// K1: grayscale + separable 5x5 blur + Hessian -> packed {t1, s2} + max(s^2).
// Tile 128x64, 512 threads, dynamic smem: sgray[72][136] then sg[68][132]
// overlay; shb[72][132].
// ---------------------------------------------------------------------------
__global__ void __launch_bounds__(512, 2) k_grayblur_ts(
        const float* __restrict__ x, const float* __restrict__ to_gray) {
    extern __shared__ __align__(16) float buf[];
    float* sgray = buf;              // [72][136]
    float* shb   = buf + 72 * SGS;   // [72][132]
    float* sg    = buf;              // [68][132] overlays sgray

    const int b  = blockIdx.z;
    const int i0 = blockIdx.y * 64;
    const int j0 = blockIdx.x * 128;
    const int t  = threadIdx.x;

    const float c0 = to_gray[0], c1 = to_gray[1], c2 = to_gray[2];
    const float* __restrict__ xr = x + (size_t)b * 3 * Hd * Wd;
    const float* __restrict__ xg = xr + (size_t)Hd * Wd;
    const float* __restrict__ xb = xg + (size_t)Hd * Wd;

    // Gray load: 72 rows x 34 float4-quads (halo 4). Interior blocks skip checks.
    const bool interior = (blockIdx.x > 0) & (blockIdx.x < gridDim.x - 1) &
                          (blockIdx.y > 0) & (blockIdx.y < gridDim.y - 1);
    if (interior) {
        for (int idx = t; idx < 72 * 34; idx += 512) {
            int li = idx / 34, q = idx - li * 34;
            size_t o = (size_t)(i0 + li - 4) * Wd + (j0 + q * 4 - 4);
            float4 r = *(const float4*)(xr + o);
            float4 g = *(const float4*)(xg + o);
            float4 bb = *(const float4*)(xb + o);
            float4 v;
            v.x = c0 * r.x + c1 * g.x + c2 * bb.x;
            v.y = c0 * r.y + c1 * g.y + c2 * bb.y;
            v.z = c0 * r.z + c1 * g.z + c2 * bb.z;
            v.w = c0 * r.w + c1 * g.w + c2 * bb.w;
            *(float4*)&sgray[li * SGS + q * 4] = v;
        }
    } else {
        for (int idx = t; idx < 72 * 34; idx += 512) {
            int li = idx / 34, q = idx - li * 34;
            int gi = i0 + li - 4, gjq = j0 + q * 4 - 4;
            float4 v = make_float4(0.f, 0.f, 0.f, 0.f);
            if ((unsigned)gi < Hd && (unsigned)gjq < Wd) {
                size_t o = (size_t)gi * Wd + gjq;
                float4 r = *(const float4*)(xr + o);
                float4 g = *(const float4*)(xg + o);
                float4 bb = *(const float4*)(xb + o);
                v.x = c0 * r.x + c1 * g.x + c2 * bb.x;
                v.y = c0 * r.y + c1 * g.y + c2 * bb.y;
                v.z = c0 * r.z + c1 * g.z + c2 * bb.z;
                v.w = c0 * r.w + c1 * g.w + c2 * bb.w;
            }
            *(float4*)&sgray[li * SGS + q * 4] = v;
        }
    }
    __syncthreads();

    // Horizontal 5-tap: 72 rows x 33 quads (out cols 0..131)
    for (int idx = t; idx < 72 * 33; idx += 512) {
        int li = idx / 33, q = idx - li * 33;
        const float* r = &sgray[li * SGS + q * 4];
        float4 A = *(const float4*)r;
        float4 B = *(const float4*)(r + 4);
        float4 o;
        o.x = W0 * (A.x + B.x) + W1 * (A.y + A.w) + W2 * A.z;
        o.y = W0 * (A.y + B.y) + W1 * (A.z + B.x) + W2 * A.w;
        o.z = W0 * (A.z + B.z) + W1 * (A.w + B.y) + W2 * B.x;
        o.w = W0 * (A.w + B.w) + W1 * (B.x + B.z) + W2 * B.y;
        *(float4*)&shb[li * SHS + q * 4] = o;
    }
    __syncthreads();

    // Vertical 5-tap: 17 row-quads x 132 cols -> sg (overlays dead sgray)
    for (int idx = t; idx < 17 * 132; idx += 512) {
        int rq = idx / 132, lj = idx - rq * 132;
        const float* p = &shb[rq * 4 * SHS + lj];
        float a0 = p[0], a1 = p[SHS], a2 = p[2 * SHS], a3 = p[3 * SHS];
        float a4 = p[4 * SHS], a5 = p[5 * SHS], a6 = p[6 * SHS], a7 = p[7 * SHS];
        float* o = &sg[rq * 4 * SGT + lj];
        o[0]       = W0 * (a0 + a4) + W1 * (a1 + a3) + W2 * a2;
        o[SGT]     = W0 * (a1 + a5) + W1 * (a2 + a4) + W2 * a3;
        o[2 * SGT] = W0 * (a2 + a6) + W1 * (a3 + a5) + W2 * a4;
        o[3 * SGT] = W0 * (a3 + a7) + W1 * (a4 + a6) + W2 * a5;
    }
    __syncthreads();

    // Hessian -> packed {t1, s2} + max(s2): thread owns col-pair txp, 8 rows.
    int txp = t & 63, ty = t >> 6;
    int r0 = ty * 8;
    int gj0 = j0 + 2 * txp;
    __half2* tsp = d_ts + ((size_t)b * Hd + (i0 + r0)) * Wd + gj0;
    bool jb = (gj0 < 2) | (gj0 + 1 >= Wd - 2);
    bool rowborder = (i0 == 0) | (i0 + 64 == Hd);
    float m;
    if (jb | rowborder)
        m = ts_border_run(sg, tsp, txp, r0, i0, j0);
    else
        m = ts_pair_run(sg, tsp, txp, r0);

#pragma unroll
    for (int o = 16; o > 0; o >>= 1)
        m = fmaxf(m, __shfl_xor_sync(0xffffffffu, m, o));
    __shared__ float wm[16];
    __shared__ int sflag;
    int lane = t & 31, wid = t >> 5;
    if (lane == 0) wm[wid] = m;
    __syncthreads();
    if (t == 0) {
        m = wm[0];
#pragma unroll
        for (int i = 1; i < 16; i++) m = fmaxf(m, wm[i]);
        d_blockmax[(b << 7) | (blockIdx.y << 3) | blockIdx.x] = m;
        __threadfence();
        unsigned int c = atomicAdd(&d_counter, 1u);
        sflag = (c == (unsigned)(Bd * 128 - 1));
    }
    __syncthreads();

    if (sflag) {  // last-finishing block computes gamma (self-reset counter)
        __shared__ float sbm[Bd];
        if (wid < Bd) {
            float m2 = 0.0f;
#pragma unroll
            for (int i = 0; i < 4; i++)
                m2 = fmaxf(m2, d_blockmax[(wid << 7) | (i * 32 + lane)]);
#pragma unroll
            for (int o = 16; o > 0; o >>= 1)
                m2 = fmaxf(m2, __shfl_xor_sync(0xffffffffu, m2, o));
            if (lane == 0) sbm[wid] = m2;
        }
        __syncthreads();
        if (t == 0) {
            float orall = 0.0f;
#pragma unroll
            for (int i = 0; i < Bd; i++) orall = fmaxf(orall, sbm[i]);
#pragma unroll
            for (int i = 0; i < Bd; i++) {
                float gm = (orall == 0.0f) ? 1.0f : 0.5f * sqrtf(sbm[i]);
                d_inv2g2[i] = 1.0f / (2.0f * gm * gm);
            }
            d_counter = 0;  // deterministic across graph replays
        }
    }
}

// ---------------------------------------------------------------------------
// K2: final elementwise response. 8 px/thread = 2 uint4 loads + 2 float4 stores.
// ---------------------------------------------------------------------------
__device__ __forceinline__ float fin1(float t1, float s2, float inv) {
    float vals = t1 * (1.0f - __expf(-s2 * inv));
    float f = fmaxf(0.0f, vals);
    return (f <= 0.0f) ? 1.0f : f;
}
__device__ __forceinline__ float4 fin4(uint4 raw, float inv) {
    float2 p0 = __half22float2(*reinterpret_cast<const __half2*>(&raw.x));
    float2 p1 = __half22float2(*reinterpret_cast<const __half2*>(&raw.y));
    float2 p2 = __half22float2(*reinterpret_cast<const __half2*>(&raw.z));
    float2 p3 = __half22float2(*reinterpret_cast<const __half2*>(&raw.w));
    float4 o;
    o.x = fin1(p0.x, p0.y, inv);
    o.y = fin1(p1.x, p1.y, inv);
    o.z = fin1(p2.x, p2.y, inv);
    o.w = fin1(p3.x, p3.y, inv);
    return o;
}

__global__ void __launch_bounds__(256) k_final(float* __restrict__ out) {
    const size_t i8 = (size_t)blockIdx.x * 256 + threadIdx.x;  // 8-px group
    const float inv = d_inv2g2[blockIdx.x >> 9];               // 512 blk/image

    const uint4* tp = (const uint4*)d_ts + i8 * 2;
    uint4 ra = tp[0];
    uint4 rb = tp[1];
    float4* op = (float4*)out + i8 * 2;
    op[0] = fin4(ra, inv);
    op[1] = fin4(rb, inv);
}

// ---------------------------------------------------------------------------
extern "C" void kernel_launch(void* const* d_in, const int* in_sizes, int n_in,
                              void* d_out, int out_size) {
    const float* x  = (const float*)d_in[0];
    const float* tg = (const float*)d_in[1];
    if (n_in >= 2 && in_sizes[0] == 3) {  // defensive: order per metadata
        const float* tmp = x; x = tg; tg = tmp;
    }
    float* out = (float*)d_out;

    const int smem = (72 * SGS + 72 * SHS) * 4;  // 77184 B
    cudaFuncSetAttribute(k_grayblur_ts,
                         cudaFuncAttributeMaxDynamicSharedMemorySize, smem);
    k_grayblur_ts<<<dim3(Wd / 128, Hd / 64, Bd), 512, smem>>>(x, tg);
    k_final<<<(Bd * Hd * Wd) / (256 * 8), 256>>>(out);
}